// round 1
// baseline (speedup 1.0000x reference)
#include <cuda_runtime.h>
#include <cuda_bf16.h>

// Problem constants (fixed by the dataset)
#define MAXN 100000
#define MAXE 1600000
#define HDIM 128
#define NSCAN_BLOCKS ((MAXN + 1023) / 1024)

// ---------------- scratch (device globals; no runtime allocation) ----------
__device__ float g_deg[MAXN];          // degree incl. self-loop (float)
__device__ int   g_cnt[MAXN];          // in-degree histogram (int)
__device__ int   g_rowptr[MAXN + 1];   // CSR row pointers (by dst)
__device__ int   g_fill[MAXN];         // fill cursors
__device__ int   g_col[MAXE];          // CSR column (src node)
__device__ float g_nrm[MAXE];          // per-edge GCN norm
__device__ int   g_bsum[NSCAN_BLOCKS + 1];
__device__ float g_h[(size_t)MAXN * HDIM];   // post-GEMM features
__device__ float g_x[(size_t)MAXN * HDIM];   // post-aggregate features

// ---------------- CSR build -------------------------------------------------
__global__ void k_init(int n) {
    int i = blockIdx.x * blockDim.x + threadIdx.x;
    if (i < n) { g_cnt[i] = 0; g_fill[i] = 0; }
}

__global__ void k_count(const int* __restrict__ dst, int e) {
    int i = blockIdx.x * blockDim.x + threadIdx.x;
    if (i < e) atomicAdd(&g_cnt[dst[i]], 1);
}

__global__ void k_deg(int n) {
    int i = blockIdx.x * blockDim.x + threadIdx.x;
    if (i < n) g_deg[i] = (float)(g_cnt[i] + 1);
}

// block-level exclusive scan of g_cnt -> g_rowptr (partial), block sums -> g_bsum
__global__ void k_scan1(int n) {
    int i = blockIdx.x * 1024 + threadIdx.x;
    int v = (i < n) ? g_cnt[i] : 0;
    int lane = threadIdx.x & 31, wid = threadIdx.x >> 5;
    int x = v;
    #pragma unroll
    for (int o = 1; o < 32; o <<= 1) {
        int y = __shfl_up_sync(0xFFFFFFFFu, x, o);
        if (lane >= o) x += y;
    }
    __shared__ int ws[32];
    if (lane == 31) ws[wid] = x;
    __syncthreads();
    if (wid == 0) {
        int w = ws[lane];
        #pragma unroll
        for (int o = 1; o < 32; o <<= 1) {
            int y = __shfl_up_sync(0xFFFFFFFFu, w, o);
            if (lane >= o) w += y;
        }
        ws[lane] = w;
    }
    __syncthreads();
    int prefix = (wid > 0) ? ws[wid - 1] : 0;
    int incl = x + prefix;
    if (i < n) g_rowptr[i] = incl - v;  // exclusive within block
    if (threadIdx.x == 1023) g_bsum[blockIdx.x] = incl;
}

__global__ void k_scan2(int nb) {
    if (threadIdx.x == 0 && blockIdx.x == 0) {
        int acc = 0;
        for (int b = 0; b < nb; b++) { int t = g_bsum[b]; g_bsum[b] = acc; acc += t; }
    }
}

__global__ void k_scan3(int n, int e) {
    int i = blockIdx.x * blockDim.x + threadIdx.x;
    if (i < n) g_rowptr[i] += g_bsum[i >> 10];
    if (i == 0) g_rowptr[n] = e;
}

__global__ void k_fill(const int* __restrict__ src, const int* __restrict__ dst, int e) {
    int i = blockIdx.x * blockDim.x + threadIdx.x;
    if (i >= e) return;
    int d = dst[i], s = src[i];
    int p = g_rowptr[d] + atomicAdd(&g_fill[d], 1);
    g_col[p] = s;
    g_nrm[p] = rsqrtf(g_deg[s] * g_deg[d]);
}

// ---------------- GEMM: H = X @ W + b  (X: n x 128, W: 128 x 128) ----------
#define BM 64
#define BK 32
__global__ __launch_bounds__(256) void k_gemm(const float* __restrict__ Xin,
                                              int use_global,
                                              const float* __restrict__ W,
                                              const float* __restrict__ bias,
                                              int n) {
    const float* __restrict__ X = use_global ? g_x : Xin;
    __shared__ float As[BM][BK];    // 8 KB
    __shared__ float Bs[BK][HDIM];  // 16 KB
    int tid = threadIdx.x;
    int tx = tid & 31;              // col group: cols tx*4 .. tx*4+3
    int ty = tid >> 5;              // row group: rows ty*8 .. ty*8+7
    int block_row = blockIdx.x * BM;
    float acc[8][4];
    #pragma unroll
    for (int r = 0; r < 8; r++)
        #pragma unroll
        for (int j = 0; j < 4; j++) acc[r][j] = 0.0f;

    for (int k0 = 0; k0 < HDIM; k0 += BK) {
        // load A tile: 64 x 32 floats = 512 float4, 2 per thread
        #pragma unroll
        for (int i = 0; i < 2; i++) {
            int f = tid + i * 256;
            int r = f >> 3, c = (f & 7) << 2;
            int row = block_row + r;
            float4 v = make_float4(0.f, 0.f, 0.f, 0.f);
            if (row < n) v = *(const float4*)&X[(size_t)row * HDIM + k0 + c];
            *(float4*)&As[r][c] = v;
        }
        // load B tile: 32 x 128 floats = 1024 float4, 4 per thread
        #pragma unroll
        for (int i = 0; i < 4; i++) {
            int f = tid + i * 256;
            int r = f >> 5, c = (f & 31) << 2;
            *(float4*)&Bs[r][c] = *(const float4*)&W[(size_t)(k0 + r) * HDIM + c];
        }
        __syncthreads();
        #pragma unroll
        for (int kk = 0; kk < BK; kk++) {
            float4 b4 = *(float4*)&Bs[kk][tx << 2];
            float a[8];
            #pragma unroll
            for (int r = 0; r < 8; r++) a[r] = As[(ty << 3) + r][kk];
            #pragma unroll
            for (int r = 0; r < 8; r++) {
                acc[r][0] += a[r] * b4.x;
                acc[r][1] += a[r] * b4.y;
                acc[r][2] += a[r] * b4.z;
                acc[r][3] += a[r] * b4.w;
            }
        }
        __syncthreads();
    }
    float4 bv = *(const float4*)&bias[tx << 2];
    #pragma unroll
    for (int r = 0; r < 8; r++) {
        int row = block_row + (ty << 3) + r;
        if (row < n) {
            float4 o;
            o.x = acc[r][0] + bv.x;
            o.y = acc[r][1] + bv.y;
            o.z = acc[r][2] + bv.z;
            o.w = acc[r][3] + bv.w;
            *(float4*)&g_h[(size_t)row * HDIM + (tx << 2)] = o;
        }
    }
}

// ---------------- aggregation: x[i] = relu( h[i]/deg[i] + sum h[src]*nrm ) --
__global__ __launch_bounds__(256) void k_aggregate(int n) {
    int gwarp = (blockIdx.x * blockDim.x + threadIdx.x) >> 5;
    int lane = threadIdx.x & 31;
    if (gwarp >= n) return;
    const float4* __restrict__ H4 = (const float4*)g_h;
    float4* __restrict__ X4 = (float4*)g_x;

    float invd = 1.0f / g_deg[gwarp];
    float4 acc = H4[(size_t)gwarp * 32 + lane];
    acc.x *= invd; acc.y *= invd; acc.z *= invd; acc.w *= invd;

    int beg = g_rowptr[gwarp], end = g_rowptr[gwarp + 1];
    for (int p = beg; p < end; p++) {
        int s = g_col[p];
        float w = g_nrm[p];
        float4 v = H4[(size_t)s * 32 + lane];
        acc.x += v.x * w; acc.y += v.y * w; acc.z += v.z * w; acc.w += v.w * w;
    }
    acc.x = fmaxf(acc.x, 0.f); acc.y = fmaxf(acc.y, 0.f);
    acc.z = fmaxf(acc.z, 0.f); acc.w = fmaxf(acc.w, 0.f);
    X4[(size_t)gwarp * 32 + lane] = acc;
}

// ---------------- segment-mean pool + 2-layer MLP head ----------------------
__device__ __forceinline__ int lbound(const int* __restrict__ a, int n, int key) {
    int lo = 0, hi = n;
    while (lo < hi) { int m = (lo + hi) >> 1; if (a[m] < key) lo = m + 1; else hi = m; }
    return lo;
}

__global__ __launch_bounds__(128) void k_pool_mlp(const int* __restrict__ batch, int n,
                                                  const float* __restrict__ Wp1,
                                                  const float* __restrict__ bp1,
                                                  const float* __restrict__ Wp2,
                                                  const float* __restrict__ bp2,
                                                  float* __restrict__ out) {
    int g = blockIdx.x;
    int t = threadIdx.x;
    int beg = lbound(batch, n, g);
    int end = lbound(batch, n, g + 1);
    float s = 0.0f;
    for (int r = beg; r < end; r++) s += g_x[(size_t)r * HDIM + t];
    float cnt = (float)(end - beg);
    float inv = 1.0f / fmaxf(cnt, 1.0f);

    __shared__ float ps[HDIM];
    ps[t] = s * inv;
    __syncthreads();

    float hid = bp1[t];
    #pragma unroll
    for (int k = 0; k < HDIM; k++) hid += ps[k] * Wp1[k * HDIM + t];
    hid = fmaxf(hid, 0.0f);

    float term = hid * Wp2[t];
    #pragma unroll
    for (int o = 16; o > 0; o >>= 1) term += __shfl_down_sync(0xFFFFFFFFu, term, o);
    __shared__ float rs[4];
    int lane = t & 31, wid = t >> 5;
    if (lane == 0) rs[wid] = term;
    __syncthreads();
    if (t == 0) out[g] = rs[0] + rs[1] + rs[2] + rs[3] + bp2[0];
}

// ---------------- launch -----------------------------------------------------
extern "C" void kernel_launch(void* const* d_in, const int* in_sizes, int n_in,
                              void* d_out, int out_size) {
    const float* x     = (const float*)d_in[0];
    const int*   ei    = (const int*)d_in[1];
    const int*   batch = (const int*)d_in[2];
    const float* Ws[3] = {(const float*)d_in[3], (const float*)d_in[5], (const float*)d_in[7]};
    const float* bs[3] = {(const float*)d_in[4], (const float*)d_in[6], (const float*)d_in[8]};
    const float* Wp1 = (const float*)d_in[9];
    const float* bp1 = (const float*)d_in[10];
    const float* Wp2 = (const float*)d_in[11];
    const float* bp2 = (const float*)d_in[12];
    float* out = (float*)d_out;

    int n = in_sizes[0] / HDIM;
    int e = in_sizes[1] / 2;
    const int* src = ei;
    const int* dst = ei + e;

    int nb_n = (n + 255) / 256;
    int nb_e = (e + 255) / 256;
    int nscan = (n + 1023) / 1024;

    // CSR build
    k_init<<<nb_n, 256>>>(n);
    k_count<<<nb_e, 256>>>(dst, e);
    k_deg<<<nb_n, 256>>>(n);
    k_scan1<<<nscan, 1024>>>(n);
    k_scan2<<<1, 32>>>(nscan);
    k_scan3<<<nb_n, 256>>>(n, e);
    k_fill<<<nb_e, 256>>>(src, dst, e);

    // 3 GCN layers
    int gemm_blocks = (n + BM - 1) / BM;
    int agg_blocks = (n + 7) / 8;  // 8 warps per 256-thread block, warp per node
    for (int l = 0; l < 3; l++) {
        k_gemm<<<gemm_blocks, 256>>>(x, l > 0 ? 1 : 0, Ws[l], bs[l], n);
        k_aggregate<<<agg_blocks, 256>>>(n);
    }

    // pool + MLP head
    k_pool_mlp<<<out_size, 128>>>(batch, n, Wp1, bp1, Wp2, bp2, out);
}